// round 12
// baseline (speedup 1.0000x reference)
#include <cuda_runtime.h>
#include <cstddef>
#include <cstdint>

#define NPF 60000
#define NGW 300000
#define NSW 60000

// ---------------- scratch layout (4-byte units, ALL multiples of 4) ----------------
// types: 0 pf_gw, 1 sw_gw, 2 gw_gw (dst gw, cap 24); 3 gw_pf, 4 sw_pf, 5 pf_sw, 6 gw_sw (cap 64)
static const size_t OFF_H1     = 0;             // 26,880,000 floats
static const size_t OFF_FILL   = 26880000;      // 1,140,000 ints
static const size_t OFF_COLIDX = 28020000;      // 36,960,000 ints
static const size_t OFF_WCAT   = 64980000;      // ~62,000 (16B aligned)

__device__ float g_scratch[65100000];   // ~260 MB

struct Ptrs7i { const int* p[7]; };
struct Ptrs7o { int* p[7]; };
struct Caps7 { int c[7]; };

// ---------------- direct bucketed adjacency build (1 kernel) ----------------
__global__ void scatter_direct(Ptrs7i ei, Ptrs7o fill, Ptrs7o col, Caps7 caps, int E) {
    int t = blockIdx.y;
    int i = blockIdx.x * blockDim.x + threadIdx.x;
    if (i < E) {
        int s = ei.p[t][i];
        int d = ei.p[t][E + i];
        int cap = caps.c[t];
        int pos = atomicAdd(&fill.p[t][d], 1);
        if (pos < cap) col.p[t][(size_t)d * cap + pos] = s;
    }
}

// ---------------- combined weights (batched) ----------------
struct WCfg {
    const float* Wl; const float* Wr; const float* b;
    float* w; float* bc;
    int Din, nm, selfid, m0, m1, m2;
};
struct WAll { WCfg c[6]; };

__global__ void build_wcat_all(WAll wa) {
    WCfg cf = wa.c[blockIdx.y];
    int K = (cf.nm + 1) * cf.Din;
    int idx = blockIdx.x * blockDim.x + threadIdx.x;
    if (idx >= 64 * K) return;
    int d = idx / K, c = idx % K;
    int seg = c / cf.Din, k = c % cf.Din;
    int ms[3] = {cf.m0, cf.m1, cf.m2};
    int stride = 64 * cf.Din;
    float v;
    if (seg < cf.nm) {
        v = cf.Wl[ms[seg] * stride + d * cf.Din + k];
    } else {
        v = cf.Wl[cf.selfid * stride + d * cf.Din + k] + cf.Wr[cf.selfid * stride + d * cf.Din + k];
        for (int i = 0; i < cf.nm; i++) v += cf.Wr[ms[i] * stride + d * cf.Din + k];
    }
    cf.w[d * K + c] = v;
    if (c == 0) {
        float bb = cf.b[cf.selfid * 64 + d];
        for (int i = 0; i < cf.nm; i++) bb += cf.b[ms[i] * 64 + d];
        cf.bc[d] = bb;
    }
}

// ---------------- fused gather + tf32 GEMM (segment-streamed, multi-type) -------------
__device__ __forceinline__ float to_tf32(float x) {
    float r;
    asm("cvt.rna.tf32.f32 %0, %1;" : "=f"(r) : "f"(x));
    return r;
}

__device__ __forceinline__ void mma_tf32(float& d0, float& d1, float& d2, float& d3,
                                         uint32_t a0, uint32_t a1, uint32_t a2, uint32_t a3,
                                         uint32_t b0, uint32_t b1) {
    asm volatile("mma.sync.aligned.m16n8k8.row.col.f32.tf32.tf32.f32 "
                 "{%0,%1,%2,%3}, {%4,%5,%6,%7}, {%8,%9}, {%0,%1,%2,%3};"
                 : "+f"(d0), "+f"(d1), "+f"(d2), "+f"(d3)
                 : "r"(a0), "r"(a1), "r"(a2), "r"(a3), "r"(b0), "r"(b1));
}

struct TypeParams {
    const int* fill[3];
    const int* ci[3];
    const float* src[3];
    const float* xself;
    const float* wcat;
    const float* bcat;
    float* out;
    int cap[3];
    int N;
    int nseg;     // edge-type segments (2 or 3)
    int K;        // (nseg+1)*DIN
    int mode;     // 0: write [N,64]; 1: prelu(dot(relu(h),linW)+linb)
    int blk0;     // first blockIdx.x for this type
};
struct LayerParams {
    TypeParams t[3];
    const float* linW; const float* linb; const float* pa;
};

// Per block: 128 dst nodes of one type. Segment-streamed K.
template <int DIN>
__global__ void __launch_bounds__(512, 3) fused_multi(LayerParams lp) {
    constexpr int S2 = DIN + 4;
    constexpr int G = DIN / 4;
    constexpr int NPI = 512 / G;
    constexpr int NIT = 128 / NPI;
    constexpr int C4 = DIN / 4;
    constexpr int BL = (64 * C4) / 512;   // 1 (DIN=32) or 2 (DIN=64)

    __shared__ float sA[128 * S2];
    __shared__ float sB[64 * S2];
    __shared__ float sred[512];

    int bx = blockIdx.x;
    int ty = (bx >= lp.t[2].blk0) ? 2 : (bx >= lp.t[1].blk0) ? 1 : 0;
    const TypeParams& tp = lp.t[ty];
    int nbase = (bx - tp.blk0) * 128;
    int N = tp.N;
    int nseg = tp.nseg;
    int K = tp.K;

    int tid = threadIdx.x;
    int warp = tid >> 5, lane = tid & 31;
    int wm = warp >> 2, wn = warp & 3;
    int r = lane >> 2, c = lane & 3;

    float acc[2][2][4];
#pragma unroll
    for (int mi = 0; mi < 2; mi++)
#pragma unroll
        for (int ni = 0; ni < 2; ni++) {
            int col = wn * 16 + ni * 8 + 2 * c;
            acc[mi][ni][0] = acc[mi][ni][2] = tp.bcat[col];
            acc[mi][ni][1] = acc[mi][ni][3] = tp.bcat[col + 1];
        }

    int g = tid & (G - 1);
    int nl0 = tid / G;

    for (int seg = 0; seg <= nseg; seg++) {
        bool isself = (seg == nseg);
        const int* fl = tp.fill[isself ? 0 : seg];
        const int* ci = tp.ci[isself ? 0 : seg];
        int cap = tp.cap[isself ? 0 : seg];
        const float* src = tp.src[isself ? 0 : seg];

        // ---- stage weight slice [64][DIN] ----
#pragma unroll
        for (int j = 0; j < BL; j++) {
            int idx = j * 512 + tid;
            int row = idx / C4, cc = idx % C4;
            float4 w = *reinterpret_cast<const float4*>(tp.wcat + (size_t)row * K + seg * DIN + cc * 4);
            float* bp = sB + row * S2 + cc * 4;
            bp[0] = to_tf32(w.x); bp[1] = to_tf32(w.y); bp[2] = to_tf32(w.z); bp[3] = to_tf32(w.w);
        }

        // ---- gather / copy A slice [128][DIN] ----
#pragma unroll
        for (int it = 0; it < NIT; it++) {
            int nl = it * NPI + nl0;
            int node = nbase + nl;
            bool valid = node < N;
            float* ar = sA + nl * S2 + g * 4;
            float4 o;
            if (!isself) {
                int deg = 0;
                if (valid) {
                    deg = fl[node];
                    deg = (deg > cap) ? cap : deg;
                }
                const int* cb = ci + (size_t)node * cap;
                float4 a4 = make_float4(0.f, 0.f, 0.f, 0.f);
                const float* sp = src + g * 4;
                int e = 0;
                for (; e + 4 <= deg; e += 4) {
                    int i0 = cb[e], i1 = cb[e + 1], i2 = cb[e + 2], i3 = cb[e + 3];
                    float4 v0 = *reinterpret_cast<const float4*>(sp + (size_t)i0 * DIN);
                    float4 v1 = *reinterpret_cast<const float4*>(sp + (size_t)i1 * DIN);
                    float4 v2 = *reinterpret_cast<const float4*>(sp + (size_t)i2 * DIN);
                    float4 v3 = *reinterpret_cast<const float4*>(sp + (size_t)i3 * DIN);
                    a4.x += (v0.x + v1.x) + (v2.x + v3.x);
                    a4.y += (v0.y + v1.y) + (v2.y + v3.y);
                    a4.z += (v0.z + v1.z) + (v2.z + v3.z);
                    a4.w += (v0.w + v1.w) + (v2.w + v3.w);
                }
                for (; e < deg; e++) {
                    int i0 = cb[e];
                    float4 v0 = *reinterpret_cast<const float4*>(sp + (size_t)i0 * DIN);
                    a4.x += v0.x; a4.y += v0.y; a4.z += v0.z; a4.w += v0.w;
                }
                float inv = (deg > 0) ? 1.0f / (float)deg : 0.0f;
                o.x = to_tf32(a4.x * inv); o.y = to_tf32(a4.y * inv);
                o.z = to_tf32(a4.z * inv); o.w = to_tf32(a4.w * inv);
            } else {
                float4 xs = make_float4(0.f, 0.f, 0.f, 0.f);
                if (valid) xs = *reinterpret_cast<const float4*>(tp.xself + (size_t)node * DIN + g * 4);
                o.x = to_tf32(xs.x); o.y = to_tf32(xs.y); o.z = to_tf32(xs.z); o.w = to_tf32(xs.w);
            }
            ar[0] = o.x; ar[1] = o.y; ar[2] = o.z; ar[3] = o.w;
        }
        __syncthreads();

        // ---- mma over this K-chunk ----
#pragma unroll
        for (int k0 = 0; k0 < DIN; k0 += 8) {
            uint32_t bf[2][2];
#pragma unroll
            for (int ni = 0; ni < 2; ni++) {
                const float* pb = sB + (wn * 16 + ni * 8 + r) * S2 + k0 + c;
                bf[ni][0] = __float_as_uint(pb[0]);
                bf[ni][1] = __float_as_uint(pb[4]);
            }
#pragma unroll
            for (int mi = 0; mi < 2; mi++) {
                const float* pav = sA + (wm * 32 + mi * 16 + r) * S2 + k0 + c;
                uint32_t a0 = __float_as_uint(pav[0]);
                uint32_t a1 = __float_as_uint(pav[8 * S2]);
                uint32_t a2 = __float_as_uint(pav[4]);
                uint32_t a3 = __float_as_uint(pav[8 * S2 + 4]);
#pragma unroll
                for (int ni = 0; ni < 2; ni++)
                    mma_tf32(acc[mi][ni][0], acc[mi][ni][1], acc[mi][ni][2], acc[mi][ni][3],
                             a0, a1, a2, a3, bf[ni][0], bf[ni][1]);
            }
        }
        __syncthreads();
    }

    // ---- epilogue ----
    float* out = tp.out;
    if (tp.mode == 0) {
#pragma unroll
        for (int mi = 0; mi < 2; mi++) {
            int m0 = nbase + wm * 32 + mi * 16 + r;
#pragma unroll
            for (int ni = 0; ni < 2; ni++) {
                int col = wn * 16 + ni * 8 + 2 * c;
                if (m0 < N) {
                    float2 v = make_float2(fmaxf(acc[mi][ni][0], 0.f), fmaxf(acc[mi][ni][1], 0.f));
                    *reinterpret_cast<float2*>(out + (size_t)m0 * 64 + col) = v;
                }
                if (m0 + 8 < N) {
                    float2 v = make_float2(fmaxf(acc[mi][ni][2], 0.f), fmaxf(acc[mi][ni][3], 0.f));
                    *reinterpret_cast<float2*>(out + (size_t)(m0 + 8) * 64 + col) = v;
                }
            }
        }
    } else {
        float lb = lp.linb[0];
        float ap = lp.pa[0];
        float pl[2] = {0.f, 0.f}, ph[2] = {0.f, 0.f};
#pragma unroll
        for (int mi = 0; mi < 2; mi++) {
#pragma unroll
            for (int ni = 0; ni < 2; ni++) {
                int col = wn * 16 + ni * 8 + 2 * c;
                float w0 = lp.linW[col], w1 = lp.linW[col + 1];
                pl[mi] += fmaxf(acc[mi][ni][0], 0.f) * w0 + fmaxf(acc[mi][ni][1], 0.f) * w1;
                ph[mi] += fmaxf(acc[mi][ni][2], 0.f) * w0 + fmaxf(acc[mi][ni][3], 0.f) * w1;
            }
            pl[mi] += __shfl_xor_sync(0xffffffffu, pl[mi], 1);
            pl[mi] += __shfl_xor_sync(0xffffffffu, pl[mi], 2);
            ph[mi] += __shfl_xor_sync(0xffffffffu, ph[mi], 1);
            ph[mi] += __shfl_xor_sync(0xffffffffu, ph[mi], 2);
        }
        if (c == 0) {
#pragma unroll
            for (int mi = 0; mi < 2; mi++) {
                sred[wn * 128 + wm * 32 + mi * 16 + r] = pl[mi];
                sred[wn * 128 + wm * 32 + mi * 16 + r + 8] = ph[mi];
            }
        }
        __syncthreads();
        if (tid < 128) {
            float v = sred[tid] + sred[128 + tid] + sred[256 + tid] + sred[384 + tid] + lb;
            int n = nbase + tid;
            if (n < N) out[n] = (v >= 0.f) ? v : ap * v;
        }
    }
}

// ---------------- launch ----------------
extern "C" void kernel_launch(void* const* d_in, const int* in_sizes, int n_in,
                              void* d_out, int out_size) {
    const float* x_pf = (const float*)d_in[0];
    const float* x_gw = (const float*)d_in[1];
    const float* x_sw = (const float*)d_in[2];
    const float* W1l  = (const float*)d_in[3];
    const float* b1l  = (const float*)d_in[4];
    const float* W1r  = (const float*)d_in[5];
    const float* W2l  = (const float*)d_in[6];
    const float* b2l  = (const float*)d_in[7];
    const float* W2r  = (const float*)d_in[8];
    const float* linW = (const float*)d_in[9];
    const float* linb = (const float*)d_in[10];
    const float* pa   = (const float*)d_in[11];
    const int* eis[7] = {
        (const int*)d_in[12],  // pf_gw
        (const int*)d_in[16],  // sw_gw
        (const int*)d_in[18],  // gw_gw
        (const int*)d_in[13],  // gw_pf
        (const int*)d_in[15],  // sw_pf
        (const int*)d_in[14],  // pf_sw
        (const int*)d_in[17],  // gw_sw
    };
    float* out = (float*)d_out;
    int E = in_sizes[12] / 2;

    float* scr;
    cudaGetSymbolAddress((void**)&scr, g_scratch);

    float* h1_pf = scr + OFF_H1;
    float* h1_gw = h1_pf + (size_t)NPF * 64;
    float* h1_sw = h1_gw + (size_t)NGW * 64;

    int* fill_base   = (int*)(scr + OFF_FILL);
    int* colidx_base = (int*)(scr + OFF_COLIDX);

    const int ns[7]   = {NGW, NGW, NGW, NPF, NPF, NSW, NSW};
    const int caps[7] = {24, 24, 24, 64, 64, 64, 64};

    Ptrs7i pei;
    Ptrs7o pfill, pcol;
    int* fills[7]; int* cols[7];
    {
        size_t foff = 0, coff = 0;
        for (int t = 0; t < 7; t++) {
            fills[t] = fill_base + foff;
            cols[t] = colidx_base + coff;
            pei.p[t] = eis[t];
            pfill.p[t] = fills[t];
            pcol.p[t] = cols[t];
            foff += (size_t)ns[t];
            coff += (size_t)ns[t] * caps[t];
        }
    }
    Caps7 pc;
    for (int t = 0; t < 7; t++) pc.c[t] = caps[t];

    float* wbase  = scr + OFF_WCAT;
    float* wL1_gw = wbase;
    float* wL1_pf = wL1_gw + 8192;
    float* wL1_sw = wL1_pf + 6144;
    float* wL2_gw = wL1_sw + 6144;
    float* wL2_pf = wL2_gw + 16384;
    float* wL2_sw = wL2_pf + 12288;
    float* bL1_gw = wL2_sw + 12288;
    float* bL1_pf = bL1_gw + 64;
    float* bL1_sw = bL1_pf + 64;
    float* bL2_gw = bL1_sw + 64;
    float* bL2_pf = bL2_gw + 64;
    float* bL2_sw = bL2_pf + 64;

    // ---- adjacency build: memset + single scatter ----
    cudaMemsetAsync(fill_base, 0, (size_t)(3 * NGW + 2 * NPF + 2 * NSW) * sizeof(int), 0);
    {
        dim3 g((E + 255) / 256, 7);
        scatter_direct<<<g, 256>>>(pei, pfill, pcol, pc, E);
    }

    // ---- weights ----
    {
        WAll wa;
        wa.c[0] = {W1l, W1r, b1l, wL1_gw, bL1_gw, 32, 3, 7, 0, 4, 6};
        wa.c[1] = {W1l, W1r, b1l, wL1_pf, bL1_pf, 32, 2, 9, 1, 3, -1};
        wa.c[2] = {W1l, W1r, b1l, wL1_sw, bL1_sw, 32, 2, 8, 2, 5, -1};
        wa.c[3] = {W2l, W2r, b2l, wL2_gw, bL2_gw, 64, 3, 7, 0, 4, 6};
        wa.c[4] = {W2l, W2r, b2l, wL2_pf, bL2_pf, 64, 2, 9, 1, 3, -1};
        wa.c[5] = {W2l, W2r, b2l, wL2_sw, bL2_sw, 64, 2, 8, 2, 5, -1};
        dim3 g(64, 6);
        build_wcat_all<<<g, 256>>>(wa);
    }

    const int BGW = (NGW + 127) / 128;   // 2344
    const int BPF = (NPF + 127) / 128;   // 469
    const int BSW = (NSW + 127) / 128;   // 469
    const int BTOT = BGW + BPF + BSW;    // 3282

    // ---- layer 1 (Din=32): one launch, 3 types ----
    {
        LayerParams lp;
        lp.linW = linW; lp.linb = linb; lp.pa = pa;
        lp.t[0] = {{fills[0], fills[1], fills[2]}, {cols[0], cols[1], cols[2]},
                   {x_pf, x_sw, x_gw}, x_gw, wL1_gw, bL1_gw, h1_gw,
                   {24, 24, 24}, NGW, 3, 128, 0, 0};
        lp.t[1] = {{fills[3], fills[4], fills[4]}, {cols[3], cols[4], cols[4]},
                   {x_gw, x_sw, x_sw}, x_pf, wL1_pf, bL1_pf, h1_pf,
                   {64, 64, 64}, NPF, 2, 96, 0, BGW};
        lp.t[2] = {{fills[5], fills[6], fills[6]}, {cols[5], cols[6], cols[6]},
                   {x_pf, x_gw, x_gw}, x_sw, wL1_sw, bL1_sw, h1_sw,
                   {64, 64, 64}, NSW, 2, 96, 0, BGW + BPF};
        fused_multi<32><<<BTOT, 512>>>(lp);
    }

    // ---- layer 2 (Din=64): one launch, 3 types ----
    // out layout: out_gw [NGW], out_sw [NSW], h_pf [NPF*64]
    {
        LayerParams lp;
        lp.linW = linW; lp.linb = linb; lp.pa = pa;
        lp.t[0] = {{fills[0], fills[1], fills[2]}, {cols[0], cols[1], cols[2]},
                   {h1_pf, h1_sw, h1_gw}, h1_gw, wL2_gw, bL2_gw, out,
                   {24, 24, 24}, NGW, 3, 256, 1, 0};
        lp.t[1] = {{fills[3], fills[4], fills[4]}, {cols[3], cols[4], cols[4]},
                   {h1_gw, h1_sw, h1_sw}, h1_pf, wL2_pf, bL2_pf, out + NGW + NSW,
                   {64, 64, 64}, NPF, 2, 192, 0, BGW};
        lp.t[2] = {{fills[5], fills[6], fills[6]}, {cols[5], cols[6], cols[6]},
                   {h1_pf, h1_gw, h1_gw}, h1_sw, wL2_sw, bL2_sw, out + NGW,
                   {64, 64, 64}, NSW, 2, 192, 1, BGW + BPF};
        fused_multi<64><<<BTOT, 512>>>(lp);
    }
}

// round 13
// speedup vs baseline: 1.3640x; 1.3640x over previous
#include <cuda_runtime.h>
#include <cuda_fp16.h>
#include <cstddef>
#include <cstdint>

#define NPF 60000
#define NGW 300000
#define NSW 60000
#define EMAX 1000000

// ---------------- scratch layout (4-byte units, ALL multiples of 4) ----------------
static const size_t OFF_H1     = 0;           // h1 as fp16 halves (region sized for fp32, 2x slack)
static const size_t OFF_CNT    = 26880000;
static const size_t OFF_FILL   = 28043264;
static const size_t OFF_INCL   = 29206528;
static const size_t OFF_BSUMS  = 30369792;    // 7*512
static const size_t OFF_ROWPTR = 30373376;    // 1,140,007 used, padded to 1,140,008
static const size_t OFF_COLIDX = 31513384;    // 7,000,000
static const size_t OFF_WCAT   = 38513384;    // float-sized slots, used as halves

__device__ float g_scratch[38600000];   // ~155 MB

// types: 0 pf_gw, 1 sw_gw, 2 gw_gw, 3 gw_pf, 4 sw_pf, 5 pf_sw, 6 gw_sw
struct ScanCfg { int ps[7]; int nblk[7]; int n[7]; int rpo[7]; };
struct Ptrs7i { const int* p[7]; };
struct Ptrs7o { int* p[7]; };

// ---------------- CSR build (batched) ----------------
__global__ void count_all(Ptrs7i ei, Ptrs7o cnt, int E) {
    int t = blockIdx.y;
    int i = blockIdx.x * blockDim.x + threadIdx.x;
    if (i < E) atomicAdd(&cnt.p[t][ei.p[t][E + i]], 1);
}

__global__ void scan_partial(const int* __restrict__ cnt, int* __restrict__ incl,
                             int* __restrict__ bsums, ScanCfg sc) {
    int t = blockIdx.y;
    if ((int)blockIdx.x >= sc.nblk[t]) return;
    __shared__ int s[1024];
    int tid = threadIdx.x;
    int base = sc.ps[t] + blockIdx.x * 1024;
    int v = cnt[base + tid];
    s[tid] = v; __syncthreads();
#pragma unroll
    for (int off = 1; off < 1024; off <<= 1) {
        int t2 = (tid >= off) ? s[tid - off] : 0;
        __syncthreads();
        s[tid] += t2;
        __syncthreads();
    }
    incl[base + tid] = s[tid];
    if (tid == 1023) bsums[t * 512 + blockIdx.x] = s[1023];
}

__global__ void scan_bsums(int* __restrict__ bs, ScanCfg sc) {
    int t = blockIdx.y;
    int nb = sc.nblk[t];
    __shared__ int s[512];
    int tid = threadIdx.x;
    int v = (tid < nb) ? bs[t * 512 + tid] : 0;
    s[tid] = v; __syncthreads();
#pragma unroll
    for (int off = 1; off < 512; off <<= 1) {
        int t2 = (tid >= off) ? s[tid - off] : 0;
        __syncthreads();
        s[tid] += t2;
        __syncthreads();
    }
    if (tid < nb) bs[t * 512 + tid] = s[tid] - v;   // exclusive
}

__global__ void scan_final(const int* __restrict__ incl, const int* __restrict__ bs,
                           int* __restrict__ rowptr, ScanCfg sc) {
    int t = blockIdx.y;
    int i = blockIdx.x * blockDim.x + threadIdx.x;
    int n = sc.n[t];
    if (i < n) rowptr[sc.rpo[t] + i + 1] = incl[sc.ps[t] + i] + bs[t * 512 + (i >> 10)];
    if (i == 0) rowptr[sc.rpo[t]] = 0;
}

__global__ void scatter_all(Ptrs7i ei, Ptrs7i rp, Ptrs7o fill, Ptrs7o col, int E) {
    int t = blockIdx.y;
    int i = blockIdx.x * blockDim.x + threadIdx.x;
    if (i < E) {
        int s = ei.p[t][i];
        int d = ei.p[t][E + i];
        int pos = rp.p[t][d] + atomicAdd(&fill.p[t][d], 1);
        col.p[t][pos] = s;
    }
}

// ---------------- combined weights (batched, emit fp16) ----------------
struct WCfg {
    const float* Wl; const float* Wr; const float* b;
    __half* w; float* bc;
    int Din, nm, selfid, m0, m1, m2;
};
struct WAll { WCfg c[6]; };

__global__ void build_wcat_all(WAll wa) {
    WCfg cf = wa.c[blockIdx.y];
    int K = (cf.nm + 1) * cf.Din;
    int idx = blockIdx.x * blockDim.x + threadIdx.x;
    if (idx >= 64 * K) return;
    int d = idx / K, c = idx % K;
    int seg = c / cf.Din, k = c % cf.Din;
    int ms[3] = {cf.m0, cf.m1, cf.m2};
    int stride = 64 * cf.Din;
    float v;
    if (seg < cf.nm) {
        v = cf.Wl[ms[seg] * stride + d * cf.Din + k];
    } else {
        v = cf.Wl[cf.selfid * stride + d * cf.Din + k] + cf.Wr[cf.selfid * stride + d * cf.Din + k];
        for (int i = 0; i < cf.nm; i++) v += cf.Wr[ms[i] * stride + d * cf.Din + k];
    }
    cf.w[d * K + c] = __float2half_rn(v);
    if (c == 0) {
        float bb = cf.b[cf.selfid * 64 + d];
        for (int i = 0; i < cf.nm; i++) bb += cf.b[ms[i] * 64 + d];
        cf.bc[d] = bb;
    }
}

// ---------------- fused gather + fp16 tensor GEMM ----------------
__device__ __forceinline__ void mma_f16(float& d0, float& d1, float& d2, float& d3,
                                        uint32_t a0, uint32_t a1, uint32_t a2, uint32_t a3,
                                        uint32_t b0, uint32_t b1) {
    asm volatile("mma.sync.aligned.m16n8k16.row.col.f32.f16.f16.f32 "
                 "{%0,%1,%2,%3}, {%4,%5,%6,%7}, {%8,%9}, {%0,%1,%2,%3};"
                 : "+f"(d0), "+f"(d1), "+f"(d2), "+f"(d3)
                 : "r"(a0), "r"(a1), "r"(a2), "r"(a3), "r"(b0), "r"(b1));
}

__device__ __forceinline__ void acc_h4(float4& a, uint2 rw) {
    __half2 h0 = *reinterpret_cast<__half2*>(&rw.x);
    __half2 h1 = *reinterpret_cast<__half2*>(&rw.y);
    float2 f0 = __half22float2(h0);
    float2 f1 = __half22float2(h1);
    a.x += f0.x; a.y += f0.y; a.z += f1.x; a.w += f1.y;
}

struct TypeParams {
    const int* rp[3];
    const int* ci[3];
    const void* src[3];
    const void* xself;
    const __half* wcat;
    const float* bcat;
    float* out;
    int N;
    int nseg;
    int K;
    int mode;
    int blk0;
};
struct LayerParams {
    TypeParams t[3];
    const float* linW; const float* linb; const float* pa;
};

template <int DIN, bool SRCF16>
__global__ void __launch_bounds__(512, 3) fused_multi(LayerParams lp) {
    constexpr int S2 = DIN + 8;           // smem row stride in halves
    constexpr int G = DIN / 4;            // 4 elements per lane
    constexpr int NPI = 512 / G;
    constexpr int NIT = 128 / NPI;
    constexpr int C8 = DIN / 8;           // uint4 (8 halves) per weight-row chunk

    __shared__ __half sA[128 * S2];
    __shared__ __half sB[64 * S2];
    __shared__ float sred[512];

    int bx = blockIdx.x;
    int ty = (bx >= lp.t[2].blk0) ? 2 : (bx >= lp.t[1].blk0) ? 1 : 0;
    const TypeParams& tp = lp.t[ty];
    int nbase = (bx - tp.blk0) * 128;
    int N = tp.N;
    int nseg = tp.nseg;
    int K = tp.K;

    int tid = threadIdx.x;
    int warp = tid >> 5, lane = tid & 31;
    int wm = warp >> 2, wn = warp & 3;
    int r = lane >> 2, c = lane & 3;

    float acc[2][2][4];
#pragma unroll
    for (int mi = 0; mi < 2; mi++)
#pragma unroll
        for (int ni = 0; ni < 2; ni++) {
            int col = wn * 16 + ni * 8 + 2 * c;
            acc[mi][ni][0] = acc[mi][ni][2] = tp.bcat[col];
            acc[mi][ni][1] = acc[mi][ni][3] = tp.bcat[col + 1];
        }

    int g = tid & (G - 1);
    int nl0 = tid / G;

    for (int seg = 0; seg <= nseg; seg++) {
        bool isself = (seg == nseg);
        const int* rp = tp.rp[isself ? 0 : seg];
        const int* ci = tp.ci[isself ? 0 : seg];
        const void* src = tp.src[isself ? 0 : seg];

        // ---- stage fp16 weight slice [64][DIN] ----
        if (tid < 64 * C8) {
            int row = tid / C8, cc = tid % C8;
            uint4 w = *reinterpret_cast<const uint4*>(tp.wcat + (size_t)row * K + seg * DIN + cc * 8);
            *reinterpret_cast<uint4*>(&sB[(size_t)row * S2 + cc * 8]) = w;
        }

        // ---- gather / copy A slice [128][DIN] into fp16 smem ----
#pragma unroll
        for (int it = 0; it < NIT; it++) {
            int nl = it * NPI + nl0;
            int node = nbase + nl;
            bool valid = node < N;
            __half* ar = &sA[(size_t)nl * S2 + g * 4];
            uint2 stv;
            if (!isself) {
                int beg = 0, end = 0;
                if (valid) { beg = rp[node]; end = rp[node + 1]; }
                float4 a4 = make_float4(0.f, 0.f, 0.f, 0.f);
                if (SRCF16) {
                    const __half* sp = (const __half*)src + g * 4;
                    int e = beg;
                    for (; e + 4 <= end; e += 4) {
                        int i0 = ci[e], i1 = ci[e + 1], i2 = ci[e + 2], i3 = ci[e + 3];
                        uint2 v0 = *reinterpret_cast<const uint2*>(sp + (size_t)i0 * DIN);
                        uint2 v1 = *reinterpret_cast<const uint2*>(sp + (size_t)i1 * DIN);
                        uint2 v2 = *reinterpret_cast<const uint2*>(sp + (size_t)i2 * DIN);
                        uint2 v3 = *reinterpret_cast<const uint2*>(sp + (size_t)i3 * DIN);
                        acc_h4(a4, v0); acc_h4(a4, v1); acc_h4(a4, v2); acc_h4(a4, v3);
                    }
                    for (; e < end; e++) {
                        uint2 v0 = *reinterpret_cast<const uint2*>(sp + (size_t)ci[e] * DIN);
                        acc_h4(a4, v0);
                    }
                } else {
                    const float* sp = (const float*)src + g * 4;
                    int e = beg;
                    for (; e + 4 <= end; e += 4) {
                        int i0 = ci[e], i1 = ci[e + 1], i2 = ci[e + 2], i3 = ci[e + 3];
                        float4 v0 = *reinterpret_cast<const float4*>(sp + (size_t)i0 * DIN);
                        float4 v1 = *reinterpret_cast<const float4*>(sp + (size_t)i1 * DIN);
                        float4 v2 = *reinterpret_cast<const float4*>(sp + (size_t)i2 * DIN);
                        float4 v3 = *reinterpret_cast<const float4*>(sp + (size_t)i3 * DIN);
                        a4.x += (v0.x + v1.x) + (v2.x + v3.x);
                        a4.y += (v0.y + v1.y) + (v2.y + v3.y);
                        a4.z += (v0.z + v1.z) + (v2.z + v3.z);
                        a4.w += (v0.w + v1.w) + (v2.w + v3.w);
                    }
                    for (; e < end; e++) {
                        float4 v0 = *reinterpret_cast<const float4*>(sp + (size_t)ci[e] * DIN);
                        a4.x += v0.x; a4.y += v0.y; a4.z += v0.z; a4.w += v0.w;
                    }
                }
                float inv = (end > beg) ? 1.0f / (float)(end - beg) : 0.0f;
                __half2 h01 = __floats2half2_rn(a4.x * inv, a4.y * inv);
                __half2 h23 = __floats2half2_rn(a4.z * inv, a4.w * inv);
                stv.x = *reinterpret_cast<uint32_t*>(&h01);
                stv.y = *reinterpret_cast<uint32_t*>(&h23);
            } else {
                if (SRCF16) {
                    stv = make_uint2(0u, 0u);
                    if (valid) stv = *reinterpret_cast<const uint2*>((const __half*)tp.xself + (size_t)node * DIN + g * 4);
                } else {
                    float4 xs = make_float4(0.f, 0.f, 0.f, 0.f);
                    if (valid) xs = *reinterpret_cast<const float4*>((const float*)tp.xself + (size_t)node * DIN + g * 4);
                    __half2 h01 = __floats2half2_rn(xs.x, xs.y);
                    __half2 h23 = __floats2half2_rn(xs.z, xs.w);
                    stv.x = *reinterpret_cast<uint32_t*>(&h01);
                    stv.y = *reinterpret_cast<uint32_t*>(&h23);
                }
            }
            *reinterpret_cast<uint2*>(ar) = stv;
        }
        __syncthreads();

        // ---- f16 mma over this K-chunk (k16 steps) ----
#pragma unroll
        for (int k0 = 0; k0 < DIN; k0 += 16) {
            uint32_t bf0[2], bf1[2];
#pragma unroll
            for (int ni = 0; ni < 2; ni++) {
                const __half* pb = &sB[(size_t)(wn * 16 + ni * 8 + r) * S2 + k0 + 2 * c];
                bf0[ni] = *reinterpret_cast<const uint32_t*>(pb);
                bf1[ni] = *reinterpret_cast<const uint32_t*>(pb + 8);
            }
#pragma unroll
            for (int mi = 0; mi < 2; mi++) {
                const __half* pa = &sA[(size_t)(wm * 32 + mi * 16 + r) * S2 + k0 + 2 * c];
                uint32_t a0 = *reinterpret_cast<const uint32_t*>(pa);
                uint32_t a1 = *reinterpret_cast<const uint32_t*>(pa + 8 * S2);
                uint32_t a2 = *reinterpret_cast<const uint32_t*>(pa + 8);
                uint32_t a3 = *reinterpret_cast<const uint32_t*>(pa + 8 * S2 + 8);
#pragma unroll
                for (int ni = 0; ni < 2; ni++)
                    mma_f16(acc[mi][ni][0], acc[mi][ni][1], acc[mi][ni][2], acc[mi][ni][3],
                            a0, a1, a2, a3, bf0[ni], bf1[ni]);
            }
        }
        __syncthreads();
    }

    // ---- epilogue ----
    if (tp.mode == 0) {
        if (!SRCF16) {
            __half* o16 = reinterpret_cast<__half*>(tp.out);
#pragma unroll
            for (int mi = 0; mi < 2; mi++) {
                int m0 = nbase + wm * 32 + mi * 16 + r;
#pragma unroll
                for (int ni = 0; ni < 2; ni++) {
                    int col = wn * 16 + ni * 8 + 2 * c;
                    if (m0 < N) {
                        __half2 v = __floats2half2_rn(fmaxf(acc[mi][ni][0], 0.f), fmaxf(acc[mi][ni][1], 0.f));
                        *reinterpret_cast<uint32_t*>(o16 + (size_t)m0 * 64 + col) = *reinterpret_cast<uint32_t*>(&v);
                    }
                    if (m0 + 8 < N) {
                        __half2 v = __floats2half2_rn(fmaxf(acc[mi][ni][2], 0.f), fmaxf(acc[mi][ni][3], 0.f));
                        *reinterpret_cast<uint32_t*>(o16 + (size_t)(m0 + 8) * 64 + col) = *reinterpret_cast<uint32_t*>(&v);
                    }
                }
            }
        } else {
            float* outp = tp.out;
#pragma unroll
            for (int mi = 0; mi < 2; mi++) {
                int m0 = nbase + wm * 32 + mi * 16 + r;
#pragma unroll
                for (int ni = 0; ni < 2; ni++) {
                    int col = wn * 16 + ni * 8 + 2 * c;
                    if (m0 < N) {
                        float2 v = make_float2(fmaxf(acc[mi][ni][0], 0.f), fmaxf(acc[mi][ni][1], 0.f));
                        *reinterpret_cast<float2*>(outp + (size_t)m0 * 64 + col) = v;
                    }
                    if (m0 + 8 < N) {
                        float2 v = make_float2(fmaxf(acc[mi][ni][2], 0.f), fmaxf(acc[mi][ni][3], 0.f));
                        *reinterpret_cast<float2*>(outp + (size_t)(m0 + 8) * 64 + col) = v;
                    }
                }
            }
        }
    } else {
        float lb = lp.linb[0];
        float ap = lp.pa[0];
        float pl[2] = {0.f, 0.f}, ph[2] = {0.f, 0.f};
#pragma unroll
        for (int mi = 0; mi < 2; mi++) {
#pragma unroll
            for (int ni = 0; ni < 2; ni++) {
                int col = wn * 16 + ni * 8 + 2 * c;
                float w0 = lp.linW[col], w1 = lp.linW[col + 1];
                pl[mi] += fmaxf(acc[mi][ni][0], 0.f) * w0 + fmaxf(acc[mi][ni][1], 0.f) * w1;
                ph[mi] += fmaxf(acc[mi][ni][2], 0.f) * w0 + fmaxf(acc[mi][ni][3], 0.f) * w1;
            }
            pl[mi] += __shfl_xor_sync(0xffffffffu, pl[mi], 1);
            pl[mi] += __shfl_xor_sync(0xffffffffu, pl[mi], 2);
            ph[mi] += __shfl_xor_sync(0xffffffffu, ph[mi], 1);
            ph[mi] += __shfl_xor_sync(0xffffffffu, ph[mi], 2);
        }
        if (c == 0) {
#pragma unroll
            for (int mi = 0; mi < 2; mi++) {
                sred[wn * 128 + wm * 32 + mi * 16 + r] = pl[mi];
                sred[wn * 128 + wm * 32 + mi * 16 + r + 8] = ph[mi];
            }
        }
        __syncthreads();
        if (tid < 128) {
            float v = sred[tid] + sred[128 + tid] + sred[256 + tid] + sred[384 + tid] + lb;
            int n = nbase + tid;
            if (n < N) tp.out[n] = (v >= 0.f) ? v : ap * v;
        }
    }
}

// ---------------- launch ----------------
extern "C" void kernel_launch(void* const* d_in, const int* in_sizes, int n_in,
                              void* d_out, int out_size) {
    const float* x_pf = (const float*)d_in[0];
    const float* x_gw = (const float*)d_in[1];
    const float* x_sw = (const float*)d_in[2];
    const float* W1l  = (const float*)d_in[3];
    const float* b1l  = (const float*)d_in[4];
    const float* W1r  = (const float*)d_in[5];
    const float* W2l  = (const float*)d_in[6];
    const float* b2l  = (const float*)d_in[7];
    const float* W2r  = (const float*)d_in[8];
    const float* linW = (const float*)d_in[9];
    const float* linb = (const float*)d_in[10];
    const float* pa   = (const float*)d_in[11];
    const int* eis[7] = {
        (const int*)d_in[12],  // pf_gw
        (const int*)d_in[16],  // sw_gw
        (const int*)d_in[18],  // gw_gw
        (const int*)d_in[13],  // gw_pf
        (const int*)d_in[15],  // sw_pf
        (const int*)d_in[14],  // pf_sw
        (const int*)d_in[17],  // gw_sw
    };
    float* out = (float*)d_out;
    int E = in_sizes[12] / 2;

    float* scr;
    cudaGetSymbolAddress((void**)&scr, g_scratch);

    __half* h1_pf = reinterpret_cast<__half*>(scr + OFF_H1);
    __half* h1_gw = h1_pf + (size_t)NPF * 64;
    __half* h1_sw = h1_gw + (size_t)NGW * 64;

    int* cnt_base    = (int*)(scr + OFF_CNT);
    int* fill_base   = (int*)(scr + OFF_FILL);
    int* incl        = (int*)(scr + OFF_INCL);
    int* bsums       = (int*)(scr + OFF_BSUMS);
    int* rowptr_base = (int*)(scr + OFF_ROWPTR);
    int* colidx_base = (int*)(scr + OFF_COLIDX);

    const int ns[7] = {NGW, NGW, NGW, NPF, NPF, NSW, NSW};
    ScanCfg sc;
    int cnt_pad_total = 0;
    {
        int po = 0, ro = 0;
        for (int t = 0; t < 7; t++) {
            sc.ps[t] = po;
            sc.n[t] = ns[t];
            sc.nblk[t] = (ns[t] + 1023) / 1024;
            sc.rpo[t] = ro;
            po += sc.nblk[t] * 1024;
            ro += ns[t] + 1;
        }
        cnt_pad_total = po;
    }

    Ptrs7i pei, prp;
    Ptrs7o pcnt, pfill, pcol;
    int* rps[7]; int* cols[7];
    for (int t = 0; t < 7; t++) {
        pei.p[t]  = eis[t];
        pcnt.p[t] = cnt_base + sc.ps[t];
        pfill.p[t] = fill_base + sc.ps[t];
        rps[t] = rowptr_base + sc.rpo[t];
        prp.p[t] = rps[t];
        cols[t] = colidx_base + (size_t)t * EMAX;
        pcol.p[t] = cols[t];
    }

    // weight regions: float-sized slots, used as halves (2x slack). bcat fp32.
    float* wbase  = scr + OFF_WCAT;
    __half* wL1_gw = (__half*)(wbase);
    __half* wL1_pf = (__half*)(wbase + 8192);
    __half* wL1_sw = (__half*)(wbase + 14336);
    __half* wL2_gw = (__half*)(wbase + 20480);
    __half* wL2_pf = (__half*)(wbase + 36864);
    __half* wL2_sw = (__half*)(wbase + 49152);
    float* bL1_gw = wbase + 61440;
    float* bL1_pf = bL1_gw + 64;
    float* bL1_sw = bL1_pf + 64;
    float* bL2_gw = bL1_sw + 64;
    float* bL2_pf = bL2_gw + 64;
    float* bL2_sw = bL2_pf + 64;

    // ---- CSR build ----
    cudaMemsetAsync(cnt_base, 0, (size_t)cnt_pad_total * sizeof(int), 0);
    cudaMemsetAsync(fill_base, 0, (size_t)cnt_pad_total * sizeof(int), 0);
    {
        dim3 g((E + 255) / 256, 7);
        count_all<<<g, 256>>>(pei, pcnt, E);
    }
    {
        dim3 g(300, 7);
        scan_partial<<<g, 1024>>>(cnt_base, incl, bsums, sc);
        dim3 g2(1, 7);
        scan_bsums<<<g2, 512>>>(bsums, sc);
        dim3 g3((NGW + 255) / 256, 7);
        scan_final<<<g3, 256>>>(incl, bsums, rowptr_base, sc);
    }
    {
        dim3 g((E + 255) / 256, 7);
        scatter_all<<<g, 256>>>(pei, prp, pfill, pcol, E);
    }

    // ---- weights (fp16) ----
    {
        WAll wa;
        wa.c[0] = {W1l, W1r, b1l, wL1_gw, bL1_gw, 32, 3, 7, 0, 4, 6};
        wa.c[1] = {W1l, W1r, b1l, wL1_pf, bL1_pf, 32, 2, 9, 1, 3, -1};
        wa.c[2] = {W1l, W1r, b1l, wL1_sw, bL1_sw, 32, 2, 8, 2, 5, -1};
        wa.c[3] = {W2l, W2r, b2l, wL2_gw, bL2_gw, 64, 3, 7, 0, 4, 6};
        wa.c[4] = {W2l, W2r, b2l, wL2_pf, bL2_pf, 64, 2, 9, 1, 3, -1};
        wa.c[5] = {W2l, W2r, b2l, wL2_sw, bL2_sw, 64, 2, 8, 2, 5, -1};
        dim3 g(64, 6);
        build_wcat_all<<<g, 256>>>(wa);
    }

    const int BGW = (NGW + 127) / 128;   // 2344
    const int BPF = (NPF + 127) / 128;   // 469
    const int BSW = (NSW + 127) / 128;   // 469
    const int BTOT = BGW + BPF + BSW;    // 3282

    // ---- layer 1 (Din=32, fp32 x -> fp16 h1) ----
    {
        LayerParams lp;
        lp.linW = linW; lp.linb = linb; lp.pa = pa;
        lp.t[0] = {{rps[0], rps[1], rps[2]}, {cols[0], cols[1], cols[2]},
                   {x_pf, x_sw, x_gw}, x_gw, wL1_gw, bL1_gw, (float*)h1_gw,
                   NGW, 3, 128, 0, 0};
        lp.t[1] = {{rps[3], rps[4], rps[4]}, {cols[3], cols[4], cols[4]},
                   {x_gw, x_sw, x_sw}, x_pf, wL1_pf, bL1_pf, (float*)h1_pf,
                   NPF, 2, 96, 0, BGW};
        lp.t[2] = {{rps[5], rps[6], rps[6]}, {cols[5], cols[6], cols[6]},
                   {x_pf, x_gw, x_gw}, x_sw, wL1_sw, bL1_sw, (float*)h1_sw,
                   NSW, 2, 96, 0, BGW + BPF};
        fused_multi<32, false><<<BTOT, 512>>>(lp);
    }

    // ---- layer 2 (Din=64, fp16 h1 sources) ----
    // out layout: out_gw [NGW], out_sw [NSW], h_pf [NPF*64]
    {
        LayerParams lp;
        lp.linW = linW; lp.linb = linb; lp.pa = pa;
        lp.t[0] = {{rps[0], rps[1], rps[2]}, {cols[0], cols[1], cols[2]},
                   {h1_pf, h1_sw, h1_gw}, h1_gw, wL2_gw, bL2_gw, out,
                   NGW, 3, 256, 1, 0};
        lp.t[1] = {{rps[3], rps[4], rps[4]}, {cols[3], cols[4], cols[4]},
                   {h1_gw, h1_sw, h1_sw}, h1_pf, wL2_pf, bL2_pf, out + NGW + NSW,
                   NPF, 2, 192, 0, BGW};
        lp.t[2] = {{rps[5], rps[6], rps[6]}, {cols[5], cols[6], cols[6]},
                   {h1_pf, h1_gw, h1_gw}, h1_sw, wL2_sw, bL2_sw, out + NGW,
                   NSW, 2, 192, 1, BGW + BPF};
        fused_multi<64, true><<<BTOT, 512>>>(lp);
    }
}